// round 12
// baseline (speedup 1.0000x reference)
#include <cuda_runtime.h>
#include <cuda_fp16.h>
#include <math.h>
#include <stdint.h>

// Problem constants
#define BATCH 4
#define NQ    1024
#define NKV   2048
#define HDIM  1024
#define NH    16
#define DHEAD 64
#define NEXP  4
#define IDIM  1024

// ---------------------------------------------------------------------------
// Scratch (device globals)
// ---------------------------------------------------------------------------
__device__ __half g_xh   [BATCH*NQ*HDIM];
__device__ __half g_qh   [BATCH*NQ*HDIM];
__device__ __half g_kh   [BATCH*NKV*HDIM];
__device__ __half g_vt   [BATCH*HDIM*NKV];       // V transposed [b][c][kv]
__device__ __half g_kvh  [BATCH*NKV*HDIM];
__device__ __half g_ctxh [BATCH*NQ*HDIM];
__device__ float  g_res  [BATCH*NQ*HDIM];
__device__ __half g_heh  [BATCH*NQ*HDIM];
__device__ __half g_inth [BATCH*NQ*IDIM];
// fp16 transposed weights ([N][K], K contiguous)
__device__ __half g_wqt  [HDIM*HDIM];
__device__ __half g_wkt  [HDIM*HDIM];
__device__ __half g_wvt  [HDIM*HDIM];
__device__ __half g_wot  [HDIM*HDIM];
__device__ __half g_gut  [NEXP*2*IDIM*HDIM];
__device__ __half g_dnt  [NEXP*HDIM*IDIM];

// ---------------------------------------------------------------------------
// helpers
// ---------------------------------------------------------------------------
__device__ __forceinline__ uint32_t smem_u32(const void* p) {
    uint32_t a;
    asm("{ .reg .u64 t; cvta.to.shared.u64 t, %1; cvt.u32.u64 %0, t; }"
        : "=r"(a) : "l"(p));
    return a;
}

__device__ __forceinline__ void cp_async16(uint32_t saddr, const void* g) {
    asm volatile("cp.async.cg.shared.global [%0], [%1], 16;\n" :: "r"(saddr), "l"(g));
}

__device__ __forceinline__ float ex2(float x) {
    float r;
    asm("ex2.approx.ftz.f32 %0, %1;" : "=f"(r) : "f"(x));
    return r;
}

__device__ __forceinline__ void ldsm_x4(uint32_t* r, uint32_t addr) {
    asm volatile("ldmatrix.sync.aligned.m8n8.x4.shared.b16 {%0,%1,%2,%3}, [%4];"
        : "=r"(r[0]), "=r"(r[1]), "=r"(r[2]), "=r"(r[3]) : "r"(addr));
}

__device__ __forceinline__ void mma_f16(float* c, const uint32_t* a, const uint32_t* b) {
    asm volatile(
        "mma.sync.aligned.m16n8k16.row.col.f32.f16.f16.f32 "
        "{%0,%1,%2,%3}, {%4,%5,%6,%7}, {%8,%9}, {%0,%1,%2,%3};"
        : "+f"(c[0]), "+f"(c[1]), "+f"(c[2]), "+f"(c[3])
        : "r"(a[0]), "r"(a[1]), "r"(a[2]), "r"(a[3]), "r"(b[0]), "r"(b[1]));
}

// per-lane byte offsets for ldmatrix (144B row stride)
__device__ __forceinline__ uint32_t lds_a_off(int lane) {
    return (uint32_t)(((lane & 7) + (lane & 8)) * 144 + ((lane & 16) ? 16 : 0));
}
__device__ __forceinline__ uint32_t lds_b_off(int lane) {
    return (uint32_t)(((lane & 7) + ((lane & 16) >> 1)) * 144 + ((lane & 8) ? 16 : 0));
}

// ---------------------------------------------------------------------------
// Fused prologue: 4 HxH weight transposes + gate_up/down transposes +
// key_value fp32->fp16 cvt + LN1. Grid-partitioned by blockIdx.x.
// ---------------------------------------------------------------------------
struct Prep {
    const float *Wq, *Wk, *Wv, *Wo, *gu, *dn, *kv, *q, *g1, *b1;
    __half *wqt, *wkt, *wvt, *wot, *gut, *dnt, *kvh, *xh;
};

__global__ __launch_bounds__(256) void prep_kernel(Prep p)
{
    __shared__ float shbuf[32 * 33];
    int id = blockIdx.x;
    const int tid = threadIdx.x;
    const int tx = tid & 31, ty = tid >> 5;

    if (id < 4096) {
        int m = id >> 10, tt = id & 1023;
        const float* in; __half* out;
        if (m == 0)      { in = p.Wq; out = p.wqt; }
        else if (m == 1) { in = p.Wk; out = p.wkt; }
        else if (m == 2) { in = p.Wv; out = p.wvt; }
        else             { in = p.Wo; out = p.wot; }
        int n0 = (tt & 31) * 32, k0 = (tt >> 5) * 32;
        #pragma unroll
        for (int i = 0; i < 32; i += 8)
            shbuf[(ty + i) * 33 + tx] = in[(long)(k0 + ty + i) * HDIM + n0 + tx];
        __syncthreads();
        #pragma unroll
        for (int i = 0; i < 32; i += 8)
            out[(long)(n0 + ty + i) * HDIM + k0 + tx] =
                __float2half(shbuf[tx * 33 + ty + i]);
    } else if (id < 4096 + 8192) {
        id -= 4096;
        int e = id >> 11, tt = id & 2047;
        const float* in = p.gu + (long)e * HDIM * 2 * IDIM;
        __half* out     = p.gut + (long)e * 2 * IDIM * HDIM;
        int n0 = (tt & 63) * 32, k0 = (tt >> 6) * 32;
        #pragma unroll
        for (int i = 0; i < 32; i += 8)
            shbuf[(ty + i) * 33 + tx] = in[(long)(k0 + ty + i) * (2 * IDIM) + n0 + tx];
        __syncthreads();
        #pragma unroll
        for (int i = 0; i < 32; i += 8) {
            int nn = n0 + ty + i;
            int orow = (nn < IDIM) ? 2 * nn : 2 * (nn - IDIM) + 1;
            out[(long)orow * HDIM + k0 + tx] = __float2half(shbuf[tx * 33 + ty + i]);
        }
    } else if (id < 4096 + 8192 + 4096) {
        id -= 4096 + 8192;
        int e = id >> 10, tt = id & 1023;
        const float* in = p.dn + (long)e * IDIM * HDIM;
        __half* out     = p.dnt + (long)e * HDIM * IDIM;
        int n0 = (tt & 31) * 32, k0 = (tt >> 5) * 32;
        #pragma unroll
        for (int i = 0; i < 32; i += 8)
            shbuf[(ty + i) * 33 + tx] = in[(long)(k0 + ty + i) * HDIM + n0 + tx];
        __syncthreads();
        #pragma unroll
        for (int i = 0; i < 32; i += 8)
            out[(long)(n0 + ty + i) * IDIM + k0 + tx] =
                __float2half(shbuf[tx * 33 + ty + i]);
    } else if (id < 4096 + 8192 + 4096 + 8192) {
        long idx = (long)(id - (4096 + 8192 + 4096)) * 256 + tid;
        float4 v = *(const float4*)&p.kv[idx * 4];
        uint2 o;
        __half2 h0 = __floats2half2_rn(v.x, v.y);
        __half2 h1 = __floats2half2_rn(v.z, v.w);
        o.x = *(uint32_t*)&h0; o.y = *(uint32_t*)&h1;
        *(uint2*)&p.kvh[idx * 4] = o;
    } else {
        int row = id - (4096 + 8192 + 4096 + 8192);
        const float* xr = p.q + (long)row * HDIM;
        float4 v = *(const float4*)&xr[tid * 4];
        float s  = v.x + v.y + v.z + v.w;
        float s2 = v.x*v.x + v.y*v.y + v.z*v.z + v.w*v.w;
        #pragma unroll
        for (int off = 16; off; off >>= 1) {
            s  += __shfl_xor_sync(0xffffffffu, s,  off);
            s2 += __shfl_xor_sync(0xffffffffu, s2, off);
        }
        float* rs  = shbuf;
        float* rs2 = shbuf + 8;
        if ((tid & 31) == 0) { rs[ty] = s; rs2[ty] = s2; }
        __syncthreads();
        float tot = 0.f, tot2 = 0.f;
        #pragma unroll
        for (int i = 0; i < 8; i++) { tot += rs[i]; tot2 += rs2[i]; }
        float mu   = tot * (1.0f / HDIM);
        float var  = tot2 * (1.0f / HDIM) - mu * mu;
        float rstd = rsqrtf(var + 1e-6f);
        float4 gv = *(const float4*)&p.g1[tid * 4];
        float4 bv = *(const float4*)&p.b1[tid * 4];
        float yx = (v.x - mu) * rstd * gv.x + bv.x;
        float yy = (v.y - mu) * rstd * gv.y + bv.y;
        float yz = (v.z - mu) * rstd * gv.z + bv.z;
        float yw = (v.w - mu) * rstd * gv.w + bv.w;
        __half* o = p.xh + (long)row * HDIM + tid * 4;
        ((__half2*)o)[0] = __floats2half2_rn(yx, yy);
        ((__half2*)o)[1] = __floats2half2_rn(yz, yw);
    }
}

// ---------------------------------------------------------------------------
// fp16 mma.sync GEMM. CTA 128x128, 8 warps (64x32 each), 256 threads.
// K-chunk 64, 144B row stride, 3-stage cp.async pipeline (depth-2 overlap).
//   mode 0: C(half)  = AB + bias
//   mode 1: C(float) = AB + bias + res
//   mode 2: C(float), MoE scatter + residual
//   mode 3: C(half)  = silu(acc_even) * acc_odd  (fused gate_up; out N/2)
//   mode 4: C(half)  = (AB + bias)^T scattered to vt[b][c][kv] (V projection)
// ---------------------------------------------------------------------------
#define GK 1024
#define NCH (GK / 64)              // 16 chunks
#define HBUF (128 * 144)           // 18432 B per matrix per stage
#define HSTAGE (2 * HBUF)          // 36864 B per stage
#define GM_SMEM (3 * HSTAGE)       // 110592 B

__device__ __forceinline__ void gl_load_h(
    const __half* A, const __half* Bt, int m0, int n0, int kc,
    uint32_t sbase, int stage, int tid)
{
    uint32_t abase = sbase + stage * HSTAGE;
    uint32_t bbase = abase + HBUF;
    const __half* ag = A  + (long)m0 * GK + kc * 64;
    const __half* bg = Bt + (long)n0 * GK + kc * 64;
    #pragma unroll
    for (int i = 0; i < 4; i++) {
        int idx = i * 256 + tid;
        int row = idx >> 3, c = idx & 7;
        uint32_t off = (uint32_t)(row * 144 + c * 16);
        cp_async16(abase + off, ag + (long)row * GK + c * 8);
        cp_async16(bbase + off, bg + (long)row * GK + c * 8);
    }
    asm volatile("cp.async.commit_group;\n" ::: "memory");
}

__global__ __launch_bounds__(256, 2) void tc_gemm_h(
    const __half* __restrict__ A, const __half* __restrict__ Bt,
    const float* __restrict__ bias, const float* __restrict__ res,
    void* __restrict__ Cv, int M, int N, int mode,
    long sA, long sB, long sC)
{
    extern __shared__ __align__(16) __half smem[];
    const int tid = threadIdx.x;
    const int z = blockIdx.z;
    A  += (long)z * sA;
    Bt += (long)z * sB;
    const int m0 = blockIdx.y * 128;
    const int n0 = blockIdx.x * 128;

    const int w    = tid >> 5;
    const int lane = tid & 31;
    const int wm   = w & 1;
    const int wn   = w >> 1;
    const int g    = lane >> 2;
    const int tig  = lane & 3;

    uint32_t sbase = smem_u32(smem);
    const uint32_t aoff = lds_a_off(lane);
    const uint32_t boff = lds_b_off(lane);

    float acc[4][4][4];
    #pragma unroll
    for (int mt = 0; mt < 4; mt++)
        #pragma unroll
        for (int nt = 0; nt < 4; nt++)
            acc[mt][nt][0] = acc[mt][nt][1] = acc[mt][nt][2] = acc[mt][nt][3] = 0.f;

    // preload two chunks (stages 0,1)
    gl_load_h(A, Bt, m0, n0, 0, sbase, 0, tid);
    gl_load_h(A, Bt, m0, n0, 1, sbase, 1, tid);

    int stage = 0;
    #pragma unroll 1
    for (int kc = 0; kc < NCH; kc++) {
        if (kc < NCH - 1)
            asm volatile("cp.async.wait_group 1;\n" ::: "memory");
        else
            asm volatile("cp.async.wait_group 0;\n" ::: "memory");
        __syncthreads();
        if (kc + 2 < NCH) {
            int nst = stage + 2; if (nst >= 3) nst -= 3;
            gl_load_h(A, Bt, m0, n0, kc + 2, sbase, nst, tid);
        }

        uint32_t Ab = sbase + stage * HSTAGE;
        uint32_t Bb = Ab + HBUF;

        #pragma unroll
        for (int ks = 0; ks < 4; ks++) {
            uint32_t af[4][4], bf[4][2];
            #pragma unroll
            for (int mt = 0; mt < 4; mt++)
                ldsm_x4(af[mt], Ab + (wm * 64 + mt * 16) * 144 + ks * 32 + aoff);
            #pragma unroll
            for (int nt2 = 0; nt2 < 2; nt2++) {
                uint32_t t4[4];
                ldsm_x4(t4, Bb + (wn * 32 + nt2 * 16) * 144 + ks * 32 + boff);
                bf[nt2 * 2][0] = t4[0]; bf[nt2 * 2][1] = t4[1];
                bf[nt2 * 2 + 1][0] = t4[2]; bf[nt2 * 2 + 1][1] = t4[3];
            }
            #pragma unroll
            for (int mt = 0; mt < 4; mt++)
                #pragma unroll
                for (int nt = 0; nt < 4; nt++)
                    mma_f16(acc[mt][nt], af[mt], bf[nt]);
        }
        // advance stage (avoid %)
        stage = stage + 1; if (stage == 3) stage = 0;
    }

    if (mode == 4) {
        // V: stage [token][chan] tile with bias, then write vt[b][chan][tok]
        __syncthreads();
        __half* st = smem;                       // [128][130]
        #pragma unroll
        for (int mt = 0; mt < 4; mt++) {
            #pragma unroll
            for (int hf = 0; hf < 2; hf++) {
                int lr = wm * 64 + mt * 16 + g + hf * 8;
                #pragma unroll
                for (int nt = 0; nt < 4; nt++) {
                    int lc = wn * 32 + nt * 8 + tig * 2;
                    float vx = acc[mt][nt][hf * 2 + 0] + bias[n0 + lc];
                    float vy = acc[mt][nt][hf * 2 + 1] + bias[n0 + lc + 1];
                    *(__half2*)&st[lr * 130 + lc] = __floats2half2_rn(vx, vy);
                }
            }
        }
        __syncthreads();
        int b     = m0 >> 11;            // 2048 tokens per batch
        int ntok0 = m0 & (NKV - 1);
        __half* vt = (__half*)Cv;
        #pragma unroll
        for (int i = tid; i < 128 * 64; i += 256) {
            int c = i >> 6, n2 = i & 63;
            __half2 v = __halves2half2(st[(n2 * 2) * 130 + c],
                                       st[(n2 * 2 + 1) * 130 + c]);
            *(__half2*)&vt[((long)b * HDIM + n0 + c) * NKV + ntok0 + n2 * 2] = v;
        }
        return;
    }

    #pragma unroll
    for (int mt = 0; mt < 4; mt++) {
        #pragma unroll
        for (int hf = 0; hf < 2; hf++) {
            int row = m0 + wm * 64 + mt * 16 + g + hf * 8;
            long rbase;
            if (mode == 2) {
                int b = row >> 8, jj = row & 255;
                rbase = (((long)b << 10) + (jj << 2) + z) * (long)HDIM;
            } else if (mode == 3) {
                rbase = (long)row * (N >> 1) + (long)z * sC;
            } else {
                rbase = (long)row * N + (long)z * sC;
            }
            #pragma unroll
            for (int nt = 0; nt < 4; nt++) {
                int col = n0 + wn * 32 + nt * 8 + tig * 2;
                float vx = acc[mt][nt][hf * 2 + 0];
                float vy = acc[mt][nt][hf * 2 + 1];
                if (bias) { vx += bias[col]; vy += bias[col + 1]; }
                if (mode == 0) {
                    *(__half2*)((__half*)Cv + rbase + col) = __floats2half2_rn(vx, vy);
                } else if (mode == 3) {
                    float sx = vx / (1.f + __expf(-vx));
                    ((__half*)Cv)[rbase + (col >> 1)] = __float2half(sx * vy);
                } else {
                    float* C = (float*)Cv;
                    const float2 rr = *(const float2*)&res[rbase + col];
                    float2 o; o.x = vx + rr.x; o.y = vy + rr.y;
                    *(float2*)&C[rbase + col] = o;
                }
            }
        }
    }
}

// ---------------------------------------------------------------------------
// LayerNorm (LN2): fp32 in -> fp16 out, expert-grouped scatter.
// ---------------------------------------------------------------------------
__global__ __launch_bounds__(256) void ln_kernel(
    const float* __restrict__ x, const float* __restrict__ g,
    const float* __restrict__ be, __half* __restrict__ out)
{
    const int row = blockIdx.x;
    const int tid = threadIdx.x;
    const float* xr = x + (long)row * HDIM;

    float4 v = *(const float4*)&xr[tid * 4];
    float s  = v.x + v.y + v.z + v.w;
    float s2 = v.x*v.x + v.y*v.y + v.z*v.z + v.w*v.w;

    #pragma unroll
    for (int off = 16; off; off >>= 1) {
        s  += __shfl_xor_sync(0xffffffffu, s,  off);
        s2 += __shfl_xor_sync(0xffffffffu, s2, off);
    }
    __shared__ float rs[8], rs2[8];
    int w = tid >> 5, lane = tid & 31;
    if (lane == 0) { rs[w] = s; rs2[w] = s2; }
    __syncthreads();
    float tot = 0.f, tot2 = 0.f;
    #pragma unroll
    for (int i = 0; i < 8; i++) { tot += rs[i]; tot2 += rs2[i]; }

    float mu   = tot * (1.0f / HDIM);
    float var  = tot2 * (1.0f / HDIM) - mu * mu;
    float rstd = rsqrtf(var + 1e-6f);

    int b = row >> 10, q = row & 1023;
    int orow = (q & 3) * (BATCH * NQ / NEXP) + b * (NQ / NEXP) + (q >> 2);

    float4 gv = *(const float4*)&g[tid * 4];
    float4 bv = *(const float4*)&be[tid * 4];
    float yx = (v.x - mu) * rstd * gv.x + bv.x;
    float yy = (v.y - mu) * rstd * gv.y + bv.y;
    float yz = (v.z - mu) * rstd * gv.z + bv.z;
    float yw = (v.w - mu) * rstd * gv.w + bv.w;
    __half* o = out + (long)orow * HDIM + tid * 4;
    ((__half2*)o)[0] = __floats2half2_rn(yx, yy);
    ((__half2*)o)[1] = __floats2half2_rn(yz, yw);
}

// ---------------------------------------------------------------------------
// fp16 tensor-core flash attention with ldmatrix. Br=128, Bc=64, d=64.
// ---------------------------------------------------------------------------
#define FQ_OFF      0
#define FK_OFF(b)   (9216 + (b) * 4608)
#define FVT_OFF(b)  (18432 + (b) * 4608)
#define FP_OFF      27648
#define FL_SMEM     ((27648 + 9216) * 2)
#define HSTF 72

__device__ __forceinline__ void fl_load_kv(
    const __half* Kh, const __half* Vt, int b, int h, int n0,
    uint32_t sbase, int buf, int tid)
{
    uint32_t kb = sbase + FK_OFF(buf) * 2;
    uint32_t vb = sbase + FVT_OFF(buf) * 2;
    const __half* kg = Kh + ((long)(b * NKV + n0) << 10) + h * DHEAD;
    const __half* vg = Vt + ((long)b * HDIM + h * DHEAD) * NKV + n0;
    #pragma unroll
    for (int i = 0; i < 2; i++) {
        int idx = i * 256 + tid;
        int row = idx >> 3, c = idx & 7;
        uint32_t off = (uint32_t)(row * 144 + c * 16);
        cp_async16(kb + off, kg + ((long)row << 10) + c * 8);
        cp_async16(vb + off, vg + (long)row * NKV + c * 8);
    }
    asm volatile("cp.async.commit_group;\n" ::: "memory");
}

__global__ __launch_bounds__(256, 2) void flash_h(
    const __half* __restrict__ Qh, const __half* __restrict__ Kh,
    const __half* __restrict__ Vt, __half* __restrict__ O)
{
    extern __shared__ __align__(16) __half fsm[];
    const int tid  = threadIdx.x;
    const int w    = tid >> 5;
    const int lane = tid & 31;
    const int g    = lane >> 2;
    const int tig  = lane & 3;
    const int q0   = blockIdx.x * 128;
    const int h    = blockIdx.y;
    const int b    = blockIdx.z;
    const float SC = 0.125f * 1.44269504088896f;

    uint32_t sbase = smem_u32(fsm);
    const uint32_t aoff = lds_a_off(lane);
    const uint32_t boff = lds_b_off(lane);

    {
        uint32_t qb = sbase + FQ_OFF;
        const __half* qg = Qh + ((long)(b * NQ + q0) << 10) + h * DHEAD;
        #pragma unroll
        for (int i = 0; i < 4; i++) {
            int idx = i * 256 + tid;
            int row = idx >> 3, c = idx & 7;
            cp_async16(qb + (uint32_t)(row * 144 + c * 16),
                       qg + ((long)row << 10) + c * 8);
        }
        asm volatile("cp.async.commit_group;\n" ::: "memory");
    }
    fl_load_kv(Kh, Vt, b, h, 0, sbase, 0, tid);
    asm volatile("cp.async.wait_group 0;\n" ::: "memory");
    __syncthreads();

    uint32_t qf[4][4];
    #pragma unroll
    for (int ks = 0; ks < 4; ks++)
        ldsm_x4(qf[ks], sbase + (w * 16) * 144 + ks * 32 + aoff);

    float m_lo = -1e30f, m_hi = -1e30f, l_lo = 0.f, l_hi = 0.f;
    float o[8][4];
    #pragma unroll
    for (int nt = 0; nt < 8; nt++)
        o[nt][0] = o[nt][1] = o[nt][2] = o[nt][3] = 0.f;

    __half* Pw = fsm + FP_OFF + w * (16 * HSTF);
    uint32_t Pb = sbase + FP_OFF * 2 + w * (16 * 144);

    #pragma unroll 1
    for (int kc = 0; kc < NKV / 64; kc++) {
        const int buf = kc & 1;
        if (kc + 1 < NKV / 64) {
            fl_load_kv(Kh, Vt, b, h, (kc + 1) * 64, sbase, buf ^ 1, tid);
            asm volatile("cp.async.wait_group 1;\n" ::: "memory");
        } else {
            asm volatile("cp.async.wait_group 0;\n" ::: "memory");
        }
        __syncthreads();

        uint32_t Kb  = sbase + FK_OFF(buf) * 2;
        uint32_t Vtb = sbase + FVT_OFF(buf) * 2;

        float sa[8][4];
        #pragma unroll
        for (int nt = 0; nt < 8; nt++)
            sa[nt][0] = sa[nt][1] = sa[nt][2] = sa[nt][3] = 0.f;
        #pragma unroll
        for (int ks = 0; ks < 4; ks++) {
            uint32_t bf[8][2];
            #pragma unroll
            for (int nt2 = 0; nt2 < 4; nt2++) {
                uint32_t t4[4];
                ldsm_x4(t4, Kb + (nt2 * 16) * 144 + ks * 32 + boff);
                bf[nt2 * 2][0] = t4[0]; bf[nt2 * 2][1] = t4[1];
                bf[nt2 * 2 + 1][0] = t4[2]; bf[nt2 * 2 + 1][1] = t4[3];
            }
            #pragma unroll
            for (int nt = 0; nt < 8; nt++)
                mma_f16(sa[nt], qf[ks], bf[nt]);
        }
        #pragma unroll
        for (int nt = 0; nt < 8; nt++) {
            sa[nt][0] *= SC; sa[nt][1] *= SC; sa[nt][2] *= SC; sa[nt][3] *= SC;
        }

        float tmx_lo = sa[0][0], tmx_hi = sa[0][2];
        #pragma unroll
        for (int nt = 0; nt < 8; nt++) {
            tmx_lo = fmaxf(tmx_lo, fmaxf(sa[nt][0], sa[nt][1]));
            tmx_hi = fmaxf(tmx_hi, fmaxf(sa[nt][2], sa[nt][3]));
        }
        tmx_lo = fmaxf(tmx_lo, __shfl_xor_sync(0xffffffffu, tmx_lo, 1));
        tmx_lo = fmaxf(tmx_lo, __shfl_xor_sync(0xffffffffu, tmx_lo, 2));
        tmx_hi = fmaxf(tmx_hi, __shfl_xor_sync(0xffffffffu, tmx_hi, 1));
        tmx_hi = fmaxf(tmx_hi, __shfl_xor_sync(0xffffffffu, tmx_hi, 2));

        float mn_lo = fmaxf(m_lo, tmx_lo);
        float mn_hi = fmaxf(m_hi, tmx_hi);
        float al_lo = ex2(m_lo - mn_lo);
        float al_hi = ex2(m_hi - mn_hi);
        m_lo = mn_lo; m_hi = mn_hi;

        float rs_lo = 0.f, rs_hi = 0.f;
        #pragma unroll
        for (int nt = 0; nt < 8; nt++) {
            float p0 = ex2(sa[nt][0] - mn_lo);
            float p1 = ex2(sa[nt][1] - mn_lo);
            float p2 = ex2(sa[nt][2] - mn_hi);
            float p3 = ex2(sa[nt][3] - mn_hi);
            rs_lo += p0 + p1;
            rs_hi += p2 + p3;
            *(__half2*)&Pw[g * HSTF + nt * 8 + tig * 2]       = __floats2half2_rn(p0, p1);
            *(__half2*)&Pw[(g + 8) * HSTF + nt * 8 + tig * 2] = __floats2half2_rn(p2, p3);
        }
        rs_lo += __shfl_xor_sync(0xffffffffu, rs_lo, 1);
        rs_lo += __shfl_xor_sync(0xffffffffu, rs_lo, 2);
        rs_hi += __shfl_xor_sync(0xffffffffu, rs_hi, 1);
        rs_hi += __shfl_xor_sync(0xffffffffu, rs_hi, 2);
        l_lo = l_lo * al_lo + rs_lo;
        l_hi = l_hi * al_hi + rs_hi;
        #pragma unroll
        for (int nt = 0; nt < 8; nt++) {
            o[nt][0] *= al_lo; o[nt][1] *= al_lo;
            o[nt][2] *= al_hi; o[nt][3] *= al_hi;
        }
        __syncwarp();

        #pragma unroll
        for (int ks = 0; ks < 4; ks++) {
            uint32_t af[4];
            ldsm_x4(af, Pb + ks * 32 + aoff);
            uint32_t bf[8][2];
            #pragma unroll
            for (int nt2 = 0; nt2 < 4; nt2++) {
                uint32_t t4[4];
                ldsm_x4(t4, Vtb + (nt2 * 16) * 144 + ks * 32 + boff);
                bf[nt2 * 2][0] = t4[0]; bf[nt2 * 2][1] = t4[1];
                bf[nt2 * 2 + 1][0] = t4[2]; bf[nt2 * 2 + 1][1] = t4[3];
            }
            #pragma unroll
            for (int nt = 0; nt < 8; nt++)
                mma_f16(o[nt], af, bf[nt]);
        }
        __syncthreads();
    }

    float il_lo = 1.0f / l_lo, il_hi = 1.0f / l_hi;
    int row_lo = q0 + w * 16 + g;
    int row_hi = row_lo + 8;
    #pragma unroll
    for (int nt = 0; nt < 8; nt++) {
        int col = h * DHEAD + nt * 8 + tig * 2;
        *(__half2*)&O[((long)(b * NQ + row_lo) << 10) + col] =
            __floats2half2_rn(o[nt][0] * il_lo, o[nt][1] * il_lo);
        *(__half2*)&O[((long)(b * NQ + row_hi) << 10) + col] =
            __floats2half2_rn(o[nt][2] * il_hi, o[nt][3] * il_hi);
    }
}

// ---------------------------------------------------------------------------
// Launch
// ---------------------------------------------------------------------------
extern "C" void kernel_launch(void* const* d_in, const int* in_sizes, int n_in,
                              void* d_out, int out_size)
{
    const float* query     = (const float*)d_in[0];
    const float* key_value = (const float*)d_in[1];
    const float* Wq = (const float*)d_in[2];
    const float* bq = (const float*)d_in[3];
    const float* Wk = (const float*)d_in[4];
    const float* bk = (const float*)d_in[5];
    const float* Wv = (const float*)d_in[6];
    const float* bv = (const float*)d_in[7];
    const float* Wo = (const float*)d_in[8];
    const float* bo = (const float*)d_in[9];
    const float* g1 = (const float*)d_in[10];
    const float* b1 = (const float*)d_in[11];
    const float* g2 = (const float*)d_in[12];
    const float* b2 = (const float*)d_in[13];
    const float* gate_up = (const float*)d_in[14];
    const float* down    = (const float*)d_in[15];
    float* out = (float*)d_out;

    __half *xh, *qh, *kh, *vt, *kvh, *ctxh, *heh, *inth;
    __half *wqt, *wkt, *wvt, *wot, *gut, *dnt;
    float *res;
    cudaGetSymbolAddress((void**)&xh,   g_xh);
    cudaGetSymbolAddress((void**)&qh,   g_qh);
    cudaGetSymbolAddress((void**)&kh,   g_kh);
    cudaGetSymbolAddress((void**)&vt,   g_vt);
    cudaGetSymbolAddress((void**)&kvh,  g_kvh);
    cudaGetSymbolAddress((void**)&ctxh, g_ctxh);
    cudaGetSymbolAddress((void**)&res,  g_res);
    cudaGetSymbolAddress((void**)&heh,  g_heh);
    cudaGetSymbolAddress((void**)&inth, g_inth);
    cudaGetSymbolAddress((void**)&wqt,  g_wqt);
    cudaGetSymbolAddress((void**)&wkt,  g_wkt);
    cudaGetSymbolAddress((void**)&wvt,  g_wvt);
    cudaGetSymbolAddress((void**)&wot,  g_wot);
    cudaGetSymbolAddress((void**)&gut,  g_gut);
    cudaGetSymbolAddress((void**)&dnt,  g_dnt);

    cudaFuncSetAttribute(flash_h,
        cudaFuncAttributeMaxDynamicSharedMemorySize, FL_SMEM);
    cudaFuncSetAttribute(tc_gemm_h,
        cudaFuncAttributeMaxDynamicSharedMemorySize, GM_SMEM);

    // 0. fused prologue (all weight transposes + kv cvt + LN1)
    Prep pp;
    pp.Wq = Wq; pp.Wk = Wk; pp.Wv = Wv; pp.Wo = Wo;
    pp.gu = gate_up; pp.dn = down; pp.kv = key_value; pp.q = query;
    pp.g1 = g1; pp.b1 = b1;
    pp.wqt = wqt; pp.wkt = wkt; pp.wvt = wvt; pp.wot = wot;
    pp.gut = gut; pp.dnt = dnt; pp.kvh = kvh; pp.xh = xh;
    prep_kernel<<<4096 + 8192 + 4096 + 8192 + 4096, 256>>>(pp);

    // 1. Q projection
    tc_gemm_h<<<dim3(8, 32), 256, GM_SMEM>>>(xh, wqt, bq, nullptr, qh,
                                             BATCH * NQ, HDIM, 0, 0, 0, 0);
    // 2. K projection
    tc_gemm_h<<<dim3(8, 64), 256, GM_SMEM>>>(kvh, wkt, bk, nullptr, kh,
                                             BATCH * NKV, HDIM, 0, 0, 0, 0);
    // 3. V projection (writes transposed into vt)
    tc_gemm_h<<<dim3(8, 64), 256, GM_SMEM>>>(kvh, wvt, bv, nullptr, vt,
                                             BATCH * NKV, HDIM, 4, 0, 0, 0);

    // 4. attention
    flash_h<<<dim3(NQ / 128, NH, BATCH), 256, FL_SMEM>>>(qh, kh, vt, ctxh);

    // 5. O proj + residual -> res (fp32)
    tc_gemm_h<<<dim3(8, 32), 256, GM_SMEM>>>(ctxh, wot, bo, query, res,
                                             BATCH * NQ, HDIM, 1, 0, 0, 0);

    // 6. LN2 (expert-grouped scatter) -> fp16
    ln_kernel<<<BATCH * NQ, 256>>>(res, g2, b2, heh);

    // 7. gate_up GEMM + fused SiLU (per expert) -> inth (half)
    tc_gemm_h<<<dim3(16, 8, NEXP), 256, GM_SMEM>>>(heh, gut, nullptr, nullptr, inth,
        BATCH * NQ / NEXP, 2 * IDIM, 3,
        (long)(BATCH * NQ / NEXP) * HDIM,
        (long)2 * IDIM * HDIM,
        (long)(BATCH * NQ / NEXP) * IDIM);

    // 8. down GEMM, scatter + residual -> out (fp32)
    tc_gemm_h<<<dim3(8, 8, NEXP), 256, GM_SMEM>>>(inth, dnt, nullptr, res, out,
        BATCH * NQ / NEXP, HDIM, 2,
        (long)(BATCH * NQ / NEXP) * IDIM,
        (long)HDIM * IDIM, 0);
}

// round 16
// speedup vs baseline: 1.0472x; 1.0472x over previous
#include <cuda_runtime.h>
#include <cuda_fp16.h>
#include <math.h>
#include <stdint.h>

// Problem constants
#define BATCH 4
#define NQ    1024
#define NKV   2048
#define HDIM  1024
#define NH    16
#define DHEAD 64
#define NEXP  4
#define IDIM  1024

// ---------------------------------------------------------------------------
// Scratch (device globals)
// ---------------------------------------------------------------------------
__device__ __half g_xh   [BATCH*NQ*HDIM];
__device__ __half g_qh   [BATCH*NQ*HDIM];
__device__ __half g_kh   [BATCH*NKV*HDIM];
__device__ __half g_vt   [BATCH*HDIM*NKV];       // V transposed [b][c][kv]
__device__ __half g_kvh  [BATCH*NKV*HDIM];
__device__ __half g_ctxh [BATCH*NQ*HDIM];
__device__ float  g_res  [BATCH*NQ*HDIM];
__device__ __half g_heh  [BATCH*NQ*HDIM];
__device__ __half g_inth [BATCH*NQ*IDIM];
// fp16 transposed weights ([N][K], K contiguous)
__device__ __half g_wqt  [HDIM*HDIM];
__device__ __half g_wkt  [HDIM*HDIM];
__device__ __half g_wvt  [HDIM*HDIM];
__device__ __half g_wot  [HDIM*HDIM];
__device__ __half g_gut  [NEXP*2*IDIM*HDIM];
__device__ __half g_dnt  [NEXP*HDIM*IDIM];

// ---------------------------------------------------------------------------
// helpers
// ---------------------------------------------------------------------------
__device__ __forceinline__ uint32_t smem_u32(const void* p) {
    uint32_t a;
    asm("{ .reg .u64 t; cvta.to.shared.u64 t, %1; cvt.u32.u64 %0, t; }"
        : "=r"(a) : "l"(p));
    return a;
}

__device__ __forceinline__ void cp_async16(uint32_t saddr, const void* g) {
    asm volatile("cp.async.cg.shared.global [%0], [%1], 16;\n" :: "r"(saddr), "l"(g));
}

__device__ __forceinline__ float ex2(float x) {
    float r;
    asm("ex2.approx.ftz.f32 %0, %1;" : "=f"(r) : "f"(x));
    return r;
}

__device__ __forceinline__ void ldsm_x4(uint32_t* r, uint32_t addr) {
    asm volatile("ldmatrix.sync.aligned.m8n8.x4.shared.b16 {%0,%1,%2,%3}, [%4];"
        : "=r"(r[0]), "=r"(r[1]), "=r"(r[2]), "=r"(r[3]) : "r"(addr));
}

__device__ __forceinline__ void mma_f16(float* c, const uint32_t* a, const uint32_t* b) {
    asm volatile(
        "mma.sync.aligned.m16n8k16.row.col.f32.f16.f16.f32 "
        "{%0,%1,%2,%3}, {%4,%5,%6,%7}, {%8,%9}, {%0,%1,%2,%3};"
        : "+f"(c[0]), "+f"(c[1]), "+f"(c[2]), "+f"(c[3])
        : "r"(a[0]), "r"(a[1]), "r"(a[2]), "r"(a[3]), "r"(b[0]), "r"(b[1]));
}

// per-lane byte offsets for ldmatrix (144B row stride)
__device__ __forceinline__ uint32_t lds_a_off(int lane) {
    return (uint32_t)(((lane & 7) + (lane & 8)) * 144 + ((lane & 16) ? 16 : 0));
}
__device__ __forceinline__ uint32_t lds_b_off(int lane) {
    return (uint32_t)(((lane & 7) + ((lane & 16) >> 1)) * 144 + ((lane & 8) ? 16 : 0));
}

// ---------------------------------------------------------------------------
// Fused prologue: weight transposes + kv cvt + LN1 (grid-partitioned)
// ---------------------------------------------------------------------------
struct Prep {
    const float *Wq, *Wk, *Wv, *Wo, *gu, *dn, *kv, *q, *g1, *b1;
    __half *wqt, *wkt, *wvt, *wot, *gut, *dnt, *kvh, *xh;
};

__global__ __launch_bounds__(256) void prep_kernel(Prep p)
{
    __shared__ float shbuf[32 * 33];
    int id = blockIdx.x;
    const int tid = threadIdx.x;
    const int tx = tid & 31, ty = tid >> 5;

    if (id < 4096) {
        int m = id >> 10, tt = id & 1023;
        const float* in; __half* out;
        if (m == 0)      { in = p.Wq; out = p.wqt; }
        else if (m == 1) { in = p.Wk; out = p.wkt; }
        else if (m == 2) { in = p.Wv; out = p.wvt; }
        else             { in = p.Wo; out = p.wot; }
        int n0 = (tt & 31) * 32, k0 = (tt >> 5) * 32;
        #pragma unroll
        for (int i = 0; i < 32; i += 8)
            shbuf[(ty + i) * 33 + tx] = in[(long)(k0 + ty + i) * HDIM + n0 + tx];
        __syncthreads();
        #pragma unroll
        for (int i = 0; i < 32; i += 8)
            out[(long)(n0 + ty + i) * HDIM + k0 + tx] =
                __float2half(shbuf[tx * 33 + ty + i]);
    } else if (id < 4096 + 8192) {
        id -= 4096;
        int e = id >> 11, tt = id & 2047;
        const float* in = p.gu + (long)e * HDIM * 2 * IDIM;
        __half* out     = p.gut + (long)e * 2 * IDIM * HDIM;
        int n0 = (tt & 63) * 32, k0 = (tt >> 6) * 32;
        #pragma unroll
        for (int i = 0; i < 32; i += 8)
            shbuf[(ty + i) * 33 + tx] = in[(long)(k0 + ty + i) * (2 * IDIM) + n0 + tx];
        __syncthreads();
        #pragma unroll
        for (int i = 0; i < 32; i += 8) {
            int nn = n0 + ty + i;
            int orow = (nn < IDIM) ? 2 * nn : 2 * (nn - IDIM) + 1;
            out[(long)orow * HDIM + k0 + tx] = __float2half(shbuf[tx * 33 + ty + i]);
        }
    } else if (id < 4096 + 8192 + 4096) {
        id -= 4096 + 8192;
        int e = id >> 10, tt = id & 1023;
        const float* in = p.dn + (long)e * IDIM * HDIM;
        __half* out     = p.dnt + (long)e * HDIM * IDIM;
        int n0 = (tt & 31) * 32, k0 = (tt >> 5) * 32;
        #pragma unroll
        for (int i = 0; i < 32; i += 8)
            shbuf[(ty + i) * 33 + tx] = in[(long)(k0 + ty + i) * HDIM + n0 + tx];
        __syncthreads();
        #pragma unroll
        for (int i = 0; i < 32; i += 8)
            out[(long)(n0 + ty + i) * IDIM + k0 + tx] =
                __float2half(shbuf[tx * 33 + ty + i]);
    } else if (id < 4096 + 8192 + 4096 + 8192) {
        long idx = (long)(id - (4096 + 8192 + 4096)) * 256 + tid;
        float4 v = *(const float4*)&p.kv[idx * 4];
        uint2 o;
        __half2 h0 = __floats2half2_rn(v.x, v.y);
        __half2 h1 = __floats2half2_rn(v.z, v.w);
        o.x = *(uint32_t*)&h0; o.y = *(uint32_t*)&h1;
        *(uint2*)&p.kvh[idx * 4] = o;
    } else {
        int row = id - (4096 + 8192 + 4096 + 8192);
        const float* xr = p.q + (long)row * HDIM;
        float4 v = *(const float4*)&xr[tid * 4];
        float s  = v.x + v.y + v.z + v.w;
        float s2 = v.x*v.x + v.y*v.y + v.z*v.z + v.w*v.w;
        #pragma unroll
        for (int off = 16; off; off >>= 1) {
            s  += __shfl_xor_sync(0xffffffffu, s,  off);
            s2 += __shfl_xor_sync(0xffffffffu, s2, off);
        }
        float* rs  = shbuf;
        float* rs2 = shbuf + 8;
        if ((tid & 31) == 0) { rs[ty] = s; rs2[ty] = s2; }
        __syncthreads();
        float tot = 0.f, tot2 = 0.f;
        #pragma unroll
        for (int i = 0; i < 8; i++) { tot += rs[i]; tot2 += rs2[i]; }
        float mu   = tot * (1.0f / HDIM);
        float var  = tot2 * (1.0f / HDIM) - mu * mu;
        float rstd = rsqrtf(var + 1e-6f);
        float4 gv = *(const float4*)&p.g1[tid * 4];
        float4 bv = *(const float4*)&p.b1[tid * 4];
        float yx = (v.x - mu) * rstd * gv.x + bv.x;
        float yy = (v.y - mu) * rstd * gv.y + bv.y;
        float yz = (v.z - mu) * rstd * gv.z + bv.z;
        float yw = (v.w - mu) * rstd * gv.w + bv.w;
        __half* o = p.xh + (long)row * HDIM + tid * 4;
        ((__half2*)o)[0] = __floats2half2_rn(yx, yy);
        ((__half2*)o)[1] = __floats2half2_rn(yz, yw);
    }
}

// ---------------------------------------------------------------------------
// Shared GEMM core: 128x128 CTA tile, 8 warps (64x32), 2-stage cp.async,
// K=1024, 144B smem row stride.
// ---------------------------------------------------------------------------
#define GK 1024
#define HBUF (128 * 144)
#define HSTAGE (2 * HBUF)
#define GM_SMEM (2 * HSTAGE)

__device__ __forceinline__ void gl_load_h(
    const __half* A, const __half* Bt, int m0, int n0, int kc,
    uint32_t sbase, int buf, int tid)
{
    uint32_t abase = sbase + buf * HSTAGE;
    uint32_t bbase = abase + HBUF;
    const __half* ag = A  + (long)m0 * GK + kc * 64;
    const __half* bg = Bt + (long)n0 * GK + kc * 64;
    #pragma unroll
    for (int i = 0; i < 4; i++) {
        int idx = i * 256 + tid;
        int row = idx >> 3, c = idx & 7;
        uint32_t off = (uint32_t)(row * 144 + c * 16);
        cp_async16(abase + off, ag + (long)row * GK + c * 8);
        cp_async16(bbase + off, bg + (long)row * GK + c * 8);
    }
    asm volatile("cp.async.commit_group;\n" ::: "memory");
}

__device__ __forceinline__ void gemm_core(
    const __half* A, const __half* Bt, int m0, int n0,
    uint32_t sbase, int tid, int wm, int wn,
    uint32_t aoff, uint32_t boff, float acc[4][4][4])
{
    #pragma unroll
    for (int mt = 0; mt < 4; mt++)
        #pragma unroll
        for (int nt = 0; nt < 4; nt++)
            acc[mt][nt][0] = acc[mt][nt][1] = acc[mt][nt][2] = acc[mt][nt][3] = 0.f;

    gl_load_h(A, Bt, m0, n0, 0, sbase, 0, tid);

    #pragma unroll 1
    for (int kc = 0; kc < GK / 64; kc++) {
        const int buf = kc & 1;
        asm volatile("cp.async.wait_group 0;\n" ::: "memory");
        __syncthreads();
        if (kc + 1 < GK / 64)
            gl_load_h(A, Bt, m0, n0, kc + 1, sbase, buf ^ 1, tid);

        uint32_t Ab = sbase + buf * HSTAGE;
        uint32_t Bb = Ab + HBUF;

        #pragma unroll
        for (int ks = 0; ks < 4; ks++) {
            uint32_t af[4][4], bf[4][2];
            #pragma unroll
            for (int mt = 0; mt < 4; mt++)
                ldsm_x4(af[mt], Ab + (wm * 64 + mt * 16) * 144 + ks * 32 + aoff);
            #pragma unroll
            for (int nt2 = 0; nt2 < 2; nt2++) {
                uint32_t t4[4];
                ldsm_x4(t4, Bb + (wn * 32 + nt2 * 16) * 144 + ks * 32 + boff);
                bf[nt2 * 2][0] = t4[0]; bf[nt2 * 2][1] = t4[1];
                bf[nt2 * 2 + 1][0] = t4[2]; bf[nt2 * 2 + 1][1] = t4[3];
            }
            #pragma unroll
            for (int mt = 0; mt < 4; mt++)
                #pragma unroll
                for (int nt = 0; nt < 4; nt++)
                    mma_f16(acc[mt][nt], af[mt], bf[nt]);
        }
    }
}

// transposed V epilogue: stage (tile+bias) then write vt[b][chan][tok]
__device__ __forceinline__ void epi_vt(
    float acc[4][4][4], __half* smem, const float* bias, __half* vt,
    int m0, int n0, int tid, int wm, int wn, int g, int tig)
{
    __syncthreads();
    __half* st = smem;                       // [128][130]
    #pragma unroll
    for (int mt = 0; mt < 4; mt++) {
        #pragma unroll
        for (int hf = 0; hf < 2; hf++) {
            int lr = wm * 64 + mt * 16 + g + hf * 8;
            #pragma unroll
            for (int nt = 0; nt < 4; nt++) {
                int lc = wn * 32 + nt * 8 + tig * 2;
                float vx = acc[mt][nt][hf * 2 + 0] + bias[n0 + lc];
                float vy = acc[mt][nt][hf * 2 + 1] + bias[n0 + lc + 1];
                *(__half2*)&st[lr * 130 + lc] = __floats2half2_rn(vx, vy);
            }
        }
    }
    __syncthreads();
    int b     = m0 >> 11;
    int ntok0 = m0 & (NKV - 1);
    #pragma unroll
    for (int i = tid; i < 128 * 64; i += 256) {
        int c = i >> 6, n2 = i & 63;
        __half2 v = __halves2half2(st[(n2 * 2) * 130 + c],
                                   st[(n2 * 2 + 1) * 130 + c]);
        *(__half2*)&vt[((long)b * HDIM + n0 + c) * NKV + ntok0 + n2 * 2] = v;
    }
}

// ---------------------------------------------------------------------------
// Merged Q/K/V projection kernel. grid (8, 160):
//   y <  32 : Q  (A=xh,  B=wqt, bias bq, out qh,  standard half epilogue)
//   y <  96 : K  (A=kvh, B=wkt, bias bk, out kh,  standard half epilogue)
//   y >= 96 : V  (A=kvh, B=wvt, bias bv, out vt,  transposed epilogue)
// ---------------------------------------------------------------------------
struct QKVArgs {
    const __half *xh, *kvh, *wqt, *wkt, *wvt;
    const float *bq, *bk, *bv;
    __half *qh, *kh, *vt;
};

__global__ __launch_bounds__(256, 2) void tc_qkv_h(QKVArgs a)
{
    extern __shared__ __align__(16) __half smem[];
    const int tid = threadIdx.x;
    const int y = blockIdx.y;
    const int n0 = blockIdx.x * 128;
    const int w    = tid >> 5;
    const int lane = tid & 31;
    const int wm   = w & 1;
    const int wn   = w >> 1;
    const int g    = lane >> 2;
    const int tig  = lane & 3;
    uint32_t sbase = smem_u32(smem);
    const uint32_t aoff = lds_a_off(lane);
    const uint32_t boff = lds_b_off(lane);

    const __half *A, *Bt;
    const float* bias;
    int m0, which;
    if (y < 32)       { A = a.xh;  Bt = a.wqt; bias = a.bq; m0 = y * 128;        which = 0; }
    else if (y < 96)  { A = a.kvh; Bt = a.wkt; bias = a.bk; m0 = (y - 32) * 128; which = 1; }
    else              { A = a.kvh; Bt = a.wvt; bias = a.bv; m0 = (y - 96) * 128; which = 2; }

    float acc[4][4][4];
    gemm_core(A, Bt, m0, n0, sbase, tid, wm, wn, aoff, boff, acc);

    if (which == 2) {
        epi_vt(acc, smem, bias, a.vt, m0, n0, tid, wm, wn, g, tig);
        return;
    }
    __half* C = (which == 0) ? a.qh : a.kh;
    #pragma unroll
    for (int mt = 0; mt < 4; mt++) {
        #pragma unroll
        for (int hf = 0; hf < 2; hf++) {
            int row = m0 + wm * 64 + mt * 16 + g + hf * 8;
            long rbase = (long)row * HDIM;
            #pragma unroll
            for (int nt = 0; nt < 4; nt++) {
                int col = n0 + wn * 32 + nt * 8 + tig * 2;
                float vx = acc[mt][nt][hf * 2 + 0] + bias[col];
                float vy = acc[mt][nt][hf * 2 + 1] + bias[col + 1];
                *(__half2*)&C[rbase + col] = __floats2half2_rn(vx, vy);
            }
        }
    }
}

// ---------------------------------------------------------------------------
// Generic GEMM kernel (O-proj, gate_up, down).
//   mode 1: C(float) = AB + bias + res
//   mode 2: C(float), MoE scatter + residual
//   mode 3: C(half)  = silu(acc_even) * acc_odd  (fused gate_up; out N/2)
// ---------------------------------------------------------------------------
__global__ __launch_bounds__(256, 2) void tc_gemm_h(
    const __half* __restrict__ A, const __half* __restrict__ Bt,
    const float* __restrict__ bias, const float* __restrict__ res,
    void* __restrict__ Cv, int M, int N, int mode,
    long sA, long sB, long sC)
{
    extern __shared__ __align__(16) __half smem[];
    const int tid = threadIdx.x;
    const int z = blockIdx.z;
    A  += (long)z * sA;
    Bt += (long)z * sB;
    const int m0 = blockIdx.y * 128;
    const int n0 = blockIdx.x * 128;
    const int w    = tid >> 5;
    const int lane = tid & 31;
    const int wm   = w & 1;
    const int wn   = w >> 1;
    const int g    = lane >> 2;
    const int tig  = lane & 3;
    uint32_t sbase = smem_u32(smem);
    const uint32_t aoff = lds_a_off(lane);
    const uint32_t boff = lds_b_off(lane);

    float acc[4][4][4];
    gemm_core(A, Bt, m0, n0, sbase, tid, wm, wn, aoff, boff, acc);

    #pragma unroll
    for (int mt = 0; mt < 4; mt++) {
        #pragma unroll
        for (int hf = 0; hf < 2; hf++) {
            int row = m0 + wm * 64 + mt * 16 + g + hf * 8;
            long rbase;
            if (mode == 2) {
                int b = row >> 8, jj = row & 255;
                rbase = (((long)b << 10) + (jj << 2) + z) * (long)HDIM;
            } else if (mode == 3) {
                rbase = (long)row * (N >> 1) + (long)z * sC;
            } else {
                rbase = (long)row * N + (long)z * sC;
            }
            #pragma unroll
            for (int nt = 0; nt < 4; nt++) {
                int col = n0 + wn * 32 + nt * 8 + tig * 2;
                float vx = acc[mt][nt][hf * 2 + 0];
                float vy = acc[mt][nt][hf * 2 + 1];
                if (bias) { vx += bias[col]; vy += bias[col + 1]; }
                if (mode == 3) {
                    float sx = vx / (1.f + __expf(-vx));
                    ((__half*)Cv)[rbase + (col >> 1)] = __float2half(sx * vy);
                } else {
                    float* C = (float*)Cv;
                    const float2 rr = *(const float2*)&res[rbase + col];
                    float2 o; o.x = vx + rr.x; o.y = vy + rr.y;
                    *(float2*)&C[rbase + col] = o;
                }
            }
        }
    }
}

// ---------------------------------------------------------------------------
// LayerNorm (LN2): fp32 in -> fp16 out, expert-grouped scatter.
// ---------------------------------------------------------------------------
__global__ __launch_bounds__(256) void ln_kernel(
    const float* __restrict__ x, const float* __restrict__ g,
    const float* __restrict__ be, __half* __restrict__ out)
{
    const int row = blockIdx.x;
    const int tid = threadIdx.x;
    const float* xr = x + (long)row * HDIM;

    float4 v = *(const float4*)&xr[tid * 4];
    float s  = v.x + v.y + v.z + v.w;
    float s2 = v.x*v.x + v.y*v.y + v.z*v.z + v.w*v.w;

    #pragma unroll
    for (int off = 16; off; off >>= 1) {
        s  += __shfl_xor_sync(0xffffffffu, s,  off);
        s2 += __shfl_xor_sync(0xffffffffu, s2, off);
    }
    __shared__ float rs[8], rs2[8];
    int w = tid >> 5, lane = tid & 31;
    if (lane == 0) { rs[w] = s; rs2[w] = s2; }
    __syncthreads();
    float tot = 0.f, tot2 = 0.f;
    #pragma unroll
    for (int i = 0; i < 8; i++) { tot += rs[i]; tot2 += rs2[i]; }

    float mu   = tot * (1.0f / HDIM);
    float var  = tot2 * (1.0f / HDIM) - mu * mu;
    float rstd = rsqrtf(var + 1e-6f);

    int b = row >> 10, q = row & 1023;
    int orow = (q & 3) * (BATCH * NQ / NEXP) + b * (NQ / NEXP) + (q >> 2);

    float4 gv = *(const float4*)&g[tid * 4];
    float4 bv = *(const float4*)&be[tid * 4];
    float yx = (v.x - mu) * rstd * gv.x + bv.x;
    float yy = (v.y - mu) * rstd * gv.y + bv.y;
    float yz = (v.z - mu) * rstd * gv.z + bv.z;
    float yw = (v.w - mu) * rstd * gv.w + bv.w;
    __half* o = out + (long)orow * HDIM + tid * 4;
    ((__half2*)o)[0] = __floats2half2_rn(yx, yy);
    ((__half2*)o)[1] = __floats2half2_rn(yz, yw);
}

// ---------------------------------------------------------------------------
// fp16 tensor-core flash attention with ldmatrix. Br=128, Bc=64, d=64.
// ---------------------------------------------------------------------------
#define FQ_OFF      0
#define FK_OFF(b)   (9216 + (b) * 4608)
#define FVT_OFF(b)  (18432 + (b) * 4608)
#define FP_OFF      27648
#define FL_SMEM     ((27648 + 9216) * 2)
#define HSTF 72

__device__ __forceinline__ void fl_load_kv(
    const __half* Kh, const __half* Vt, int b, int h, int n0,
    uint32_t sbase, int buf, int tid)
{
    uint32_t kb = sbase + FK_OFF(buf) * 2;
    uint32_t vb = sbase + FVT_OFF(buf) * 2;
    const __half* kg = Kh + ((long)(b * NKV + n0) << 10) + h * DHEAD;
    const __half* vg = Vt + ((long)b * HDIM + h * DHEAD) * NKV + n0;
    #pragma unroll
    for (int i = 0; i < 2; i++) {
        int idx = i * 256 + tid;
        int row = idx >> 3, c = idx & 7;
        uint32_t off = (uint32_t)(row * 144 + c * 16);
        cp_async16(kb + off, kg + ((long)row << 10) + c * 8);
        cp_async16(vb + off, vg + (long)row * NKV + c * 8);
    }
    asm volatile("cp.async.commit_group;\n" ::: "memory");
}

__global__ __launch_bounds__(256, 2) void flash_h(
    const __half* __restrict__ Qh, const __half* __restrict__ Kh,
    const __half* __restrict__ Vt, __half* __restrict__ O)
{
    extern __shared__ __align__(16) __half fsm[];
    const int tid  = threadIdx.x;
    const int w    = tid >> 5;
    const int lane = tid & 31;
    const int g    = lane >> 2;
    const int tig  = lane & 3;
    const int q0   = blockIdx.x * 128;
    const int h    = blockIdx.y;
    const int b    = blockIdx.z;
    const float SC = 0.125f * 1.44269504088896f;

    uint32_t sbase = smem_u32(fsm);
    const uint32_t aoff = lds_a_off(lane);
    const uint32_t boff = lds_b_off(lane);

    {
        uint32_t qb = sbase + FQ_OFF;
        const __half* qg = Qh + ((long)(b * NQ + q0) << 10) + h * DHEAD;
        #pragma unroll
        for (int i = 0; i < 4; i++) {
            int idx = i * 256 + tid;
            int row = idx >> 3, c = idx & 7;
            cp_async16(qb + (uint32_t)(row * 144 + c * 16),
                       qg + ((long)row << 10) + c * 8);
        }
        asm volatile("cp.async.commit_group;\n" ::: "memory");
    }
    fl_load_kv(Kh, Vt, b, h, 0, sbase, 0, tid);
    asm volatile("cp.async.wait_group 0;\n" ::: "memory");
    __syncthreads();

    uint32_t qf[4][4];
    #pragma unroll
    for (int ks = 0; ks < 4; ks++)
        ldsm_x4(qf[ks], sbase + (w * 16) * 144 + ks * 32 + aoff);

    float m_lo = -1e30f, m_hi = -1e30f, l_lo = 0.f, l_hi = 0.f;
    float o[8][4];
    #pragma unroll
    for (int nt = 0; nt < 8; nt++)
        o[nt][0] = o[nt][1] = o[nt][2] = o[nt][3] = 0.f;

    __half* Pw = fsm + FP_OFF + w * (16 * HSTF);
    uint32_t Pb = sbase + FP_OFF * 2 + w * (16 * 144);

    #pragma unroll 1
    for (int kc = 0; kc < NKV / 64; kc++) {
        const int buf = kc & 1;
        if (kc + 1 < NKV / 64) {
            fl_load_kv(Kh, Vt, b, h, (kc + 1) * 64, sbase, buf ^ 1, tid);
            asm volatile("cp.async.wait_group 1;\n" ::: "memory");
        } else {
            asm volatile("cp.async.wait_group 0;\n" ::: "memory");
        }
        __syncthreads();

        uint32_t Kb  = sbase + FK_OFF(buf) * 2;
        uint32_t Vtb = sbase + FVT_OFF(buf) * 2;

        float sa[8][4];
        #pragma unroll
        for (int nt = 0; nt < 8; nt++)
            sa[nt][0] = sa[nt][1] = sa[nt][2] = sa[nt][3] = 0.f;
        #pragma unroll
        for (int ks = 0; ks < 4; ks++) {
            uint32_t bf[8][2];
            #pragma unroll
            for (int nt2 = 0; nt2 < 4; nt2++) {
                uint32_t t4[4];
                ldsm_x4(t4, Kb + (nt2 * 16) * 144 + ks * 32 + boff);
                bf[nt2 * 2][0] = t4[0]; bf[nt2 * 2][1] = t4[1];
                bf[nt2 * 2 + 1][0] = t4[2]; bf[nt2 * 2 + 1][1] = t4[3];
            }
            #pragma unroll
            for (int nt = 0; nt < 8; nt++)
                mma_f16(sa[nt], qf[ks], bf[nt]);
        }
        #pragma unroll
        for (int nt = 0; nt < 8; nt++) {
            sa[nt][0] *= SC; sa[nt][1] *= SC; sa[nt][2] *= SC; sa[nt][3] *= SC;
        }

        float tmx_lo = sa[0][0], tmx_hi = sa[0][2];
        #pragma unroll
        for (int nt = 0; nt < 8; nt++) {
            tmx_lo = fmaxf(tmx_lo, fmaxf(sa[nt][0], sa[nt][1]));
            tmx_hi = fmaxf(tmx_hi, fmaxf(sa[nt][2], sa[nt][3]));
        }
        tmx_lo = fmaxf(tmx_lo, __shfl_xor_sync(0xffffffffu, tmx_lo, 1));
        tmx_lo = fmaxf(tmx_lo, __shfl_xor_sync(0xffffffffu, tmx_lo, 2));
        tmx_hi = fmaxf(tmx_hi, __shfl_xor_sync(0xffffffffu, tmx_hi, 1));
        tmx_hi = fmaxf(tmx_hi, __shfl_xor_sync(0xffffffffu, tmx_hi, 2));

        float mn_lo = fmaxf(m_lo, tmx_lo);
        float mn_hi = fmaxf(m_hi, tmx_hi);
        float al_lo = ex2(m_lo - mn_lo);
        float al_hi = ex2(m_hi - mn_hi);
        m_lo = mn_lo; m_hi = mn_hi;

        float rs_lo = 0.f, rs_hi = 0.f;
        #pragma unroll
        for (int nt = 0; nt < 8; nt++) {
            float p0 = ex2(sa[nt][0] - mn_lo);
            float p1 = ex2(sa[nt][1] - mn_lo);
            float p2 = ex2(sa[nt][2] - mn_hi);
            float p3 = ex2(sa[nt][3] - mn_hi);
            rs_lo += p0 + p1;
            rs_hi += p2 + p3;
            *(__half2*)&Pw[g * HSTF + nt * 8 + tig * 2]       = __floats2half2_rn(p0, p1);
            *(__half2*)&Pw[(g + 8) * HSTF + nt * 8 + tig * 2] = __floats2half2_rn(p2, p3);
        }
        rs_lo += __shfl_xor_sync(0xffffffffu, rs_lo, 1);
        rs_lo += __shfl_xor_sync(0xffffffffu, rs_lo, 2);
        rs_hi += __shfl_xor_sync(0xffffffffu, rs_hi, 1);
        rs_hi += __shfl_xor_sync(0xffffffffu, rs_hi, 2);
        l_lo = l_lo * al_lo + rs_lo;
        l_hi = l_hi * al_hi + rs_hi;
        #pragma unroll
        for (int nt = 0; nt < 8; nt++) {
            o[nt][0] *= al_lo; o[nt][1] *= al_lo;
            o[nt][2] *= al_hi; o[nt][3] *= al_hi;
        }
        __syncwarp();

        #pragma unroll
        for (int ks = 0; ks < 4; ks++) {
            uint32_t af[4];
            ldsm_x4(af, Pb + ks * 32 + aoff);
            uint32_t bf[8][2];
            #pragma unroll
            for (int nt2 = 0; nt2 < 4; nt2++) {
                uint32_t t4[4];
                ldsm_x4(t4, Vtb + (nt2 * 16) * 144 + ks * 32 + boff);
                bf[nt2 * 2][0] = t4[0]; bf[nt2 * 2][1] = t4[1];
                bf[nt2 * 2 + 1][0] = t4[2]; bf[nt2 * 2 + 1][1] = t4[3];
            }
            #pragma unroll
            for (int nt = 0; nt < 8; nt++)
                mma_f16(o[nt], af, bf[nt]);
        }
        __syncthreads();
    }

    float il_lo = 1.0f / l_lo, il_hi = 1.0f / l_hi;
    int row_lo = q0 + w * 16 + g;
    int row_hi = row_lo + 8;
    #pragma unroll
    for (int nt = 0; nt < 8; nt++) {
        int col = h * DHEAD + nt * 8 + tig * 2;
        *(__half2*)&O[((long)(b * NQ + row_lo) << 10) + col] =
            __floats2half2_rn(o[nt][0] * il_lo, o[nt][1] * il_lo);
        *(__half2*)&O[((long)(b * NQ + row_hi) << 10) + col] =
            __floats2half2_rn(o[nt][2] * il_hi, o[nt][3] * il_hi);
    }
}

// ---------------------------------------------------------------------------
// Launch
// ---------------------------------------------------------------------------
extern "C" void kernel_launch(void* const* d_in, const int* in_sizes, int n_in,
                              void* d_out, int out_size)
{
    const float* query     = (const float*)d_in[0];
    const float* key_value = (const float*)d_in[1];
    const float* Wq = (const float*)d_in[2];
    const float* bq = (const float*)d_in[3];
    const float* Wk = (const float*)d_in[4];
    const float* bk = (const float*)d_in[5];
    const float* Wv = (const float*)d_in[6];
    const float* bv = (const float*)d_in[7];
    const float* Wo = (const float*)d_in[8];
    const float* bo = (const float*)d_in[9];
    const float* g1 = (const float*)d_in[10];
    const float* b1 = (const float*)d_in[11];
    const float* g2 = (const float*)d_in[12];
    const float* b2 = (const float*)d_in[13];
    const float* gate_up = (const float*)d_in[14];
    const float* down    = (const float*)d_in[15];
    float* out = (float*)d_out;

    __half *xh, *qh, *kh, *vt, *kvh, *ctxh, *heh, *inth;
    __half *wqt, *wkt, *wvt, *wot, *gut, *dnt;
    float *res;
    cudaGetSymbolAddress((void**)&xh,   g_xh);
    cudaGetSymbolAddress((void**)&qh,   g_qh);
    cudaGetSymbolAddress((void**)&kh,   g_kh);
    cudaGetSymbolAddress((void**)&vt,   g_vt);
    cudaGetSymbolAddress((void**)&kvh,  g_kvh);
    cudaGetSymbolAddress((void**)&ctxh, g_ctxh);
    cudaGetSymbolAddress((void**)&res,  g_res);
    cudaGetSymbolAddress((void**)&heh,  g_heh);
    cudaGetSymbolAddress((void**)&inth, g_inth);
    cudaGetSymbolAddress((void**)&wqt,  g_wqt);
    cudaGetSymbolAddress((void**)&wkt,  g_wkt);
    cudaGetSymbolAddress((void**)&wvt,  g_wvt);
    cudaGetSymbolAddress((void**)&wot,  g_wot);
    cudaGetSymbolAddress((void**)&gut,  g_gut);
    cudaGetSymbolAddress((void**)&dnt,  g_dnt);

    cudaFuncSetAttribute(flash_h,
        cudaFuncAttributeMaxDynamicSharedMemorySize, FL_SMEM);
    cudaFuncSetAttribute(tc_gemm_h,
        cudaFuncAttributeMaxDynamicSharedMemorySize, GM_SMEM);
    cudaFuncSetAttribute(tc_qkv_h,
        cudaFuncAttributeMaxDynamicSharedMemorySize, GM_SMEM);

    // 0. fused prologue (all weight transposes + kv cvt + LN1)
    Prep pp;
    pp.Wq = Wq; pp.Wk = Wk; pp.Wv = Wv; pp.Wo = Wo;
    pp.gu = gate_up; pp.dn = down; pp.kv = key_value; pp.q = query;
    pp.g1 = g1; pp.b1 = b1;
    pp.wqt = wqt; pp.wkt = wkt; pp.wvt = wvt; pp.wot = wot;
    pp.gut = gut; pp.dnt = dnt; pp.kvh = kvh; pp.xh = xh;
    prep_kernel<<<4096 + 8192 + 4096 + 8192 + 4096, 256>>>(pp);

    // 1. merged Q+K+V projections (single launch; V writes transposed)
    QKVArgs qa;
    qa.xh = xh; qa.kvh = kvh;
    qa.wqt = wqt; qa.wkt = wkt; qa.wvt = wvt;
    qa.bq = bq; qa.bk = bk; qa.bv = bv;
    qa.qh = qh; qa.kh = kh; qa.vt = vt;
    tc_qkv_h<<<dim3(8, 160), 256, GM_SMEM>>>(qa);

    // 2. attention
    flash_h<<<dim3(NQ / 128, NH, BATCH), 256, FL_SMEM>>>(qh, kh, vt, ctxh);

    // 3. O proj + residual -> res (fp32)
    tc_gemm_h<<<dim3(8, 32), 256, GM_SMEM>>>(ctxh, wot, bo, query, res,
                                             BATCH * NQ, HDIM, 1, 0, 0, 0);

    // 4. LN2 (expert-grouped scatter) -> fp16
    ln_kernel<<<BATCH * NQ, 256>>>(res, g2, b2, heh);

    // 5. gate_up GEMM + fused SiLU (per expert) -> inth (half)
    tc_gemm_h<<<dim3(16, 8, NEXP), 256, GM_SMEM>>>(heh, gut, nullptr, nullptr, inth,
        BATCH * NQ / NEXP, 2 * IDIM, 3,
        (long)(BATCH * NQ / NEXP) * HDIM,
        (long)2 * IDIM * HDIM,
        (long)(BATCH * NQ / NEXP) * IDIM);

    // 6. down GEMM, scatter + residual -> out (fp32)
    tc_gemm_h<<<dim3(8, 8, NEXP), 256, GM_SMEM>>>(inth, dnt, nullptr, res, out,
        BATCH * NQ / NEXP, HDIM, 2,
        (long)(BATCH * NQ / NEXP) * IDIM,
        (long)HDIM * IDIM, 0);
}